// round 4
// baseline (speedup 1.0000x reference)
#include <cuda_runtime.h>
#include <math.h>

#define N_TOK 131072
#define BATCH 64
#define H 512

// Scratch (no cudaMalloc allowed): P = hidden @ W1^T  (64x512), per-token scores.
__device__ float g_P[BATCH * H];
__device__ float g_scores[N_TOK];

// ---------------- f32x2 helpers (sm_103a packed fp32) ----------------
static __device__ __forceinline__ unsigned long long f32x2_fma(
    unsigned long long a, unsigned long long b, unsigned long long c) {
  unsigned long long d;
  asm("fma.rn.f32x2 %0, %1, %2, %3;" : "=l"(d) : "l"(a), "l"(b), "l"(c));
  return d;
}
static __device__ __forceinline__ unsigned long long f32x2_dup(float x) {
  unsigned long long d;
  asm("mov.b64 %0, {%1, %1};" : "=l"(d) : "f"(x));
  return d;
}
static __device__ __forceinline__ float2 f32x2_unpack(unsigned long long vv) {
  float2 r;
  asm("mov.b64 {%0, %1}, %2;" : "=f"(r.x), "=f"(r.y) : "l"(vv));
  return r;
}

// ---------------- Kernel 1: P[b,h] = sum_k hidden[b,k] * W[h,k] ----------------
__global__ void k_precompute_P(const float* __restrict__ hidden,
                               const float* __restrict__ W) {
  int b = blockIdx.x;
  int h = threadIdx.x;  // 512 threads
  __shared__ float hs[H];
  hs[h] = hidden[b * H + h];
  __syncthreads();
  const float4* wr = reinterpret_cast<const float4*>(W + (size_t)h * (2 * H));
  float acc = 0.f;
#pragma unroll 8
  for (int k4 = 0; k4 < H / 4; k4++) {
    float4 w = wr[k4];
    const float* hh = &hs[k4 * 4];
    acc += w.x * hh[0] + w.y * hh[1] + w.z * hh[2] + w.w * hh[3];
  }
  g_P[b * H + h] = acc;
}

// ---------------- Kernel 2: fused GEMM + tanh + v-dot ----------------
// E2[n,h] = sum_k enc[n,k] * W[h, 512+k];  score[n] = sum_h v[h]*tanh(P[seg[n],h]+E2[n,h])
#define BM 128
#define BN 128
#define BK 16

__global__ __launch_bounds__(256) void k_fused(const float* __restrict__ enc,
                                               const int* __restrict__ seg,
                                               const float* __restrict__ W,
                                               const float* __restrict__ v) {
  __shared__ unsigned long long As2[BK][BM];  // duplicated {a,a} pairs, 16 KB
  __shared__ float Bs[BK][BN];                // 8 KB
  __shared__ float red[BM][16];               // 8 KB

  const int tid = threadIdx.x;
  const int tx = tid & 15;
  const int ty = tid >> 4;
  const int m0 = blockIdx.x * BM;

  int segr[8];
#pragma unroll
  for (int i = 0; i < 8; i++) segr[i] = seg[m0 + ty * 8 + i];

  float rs[8];
#pragma unroll
  for (int i = 0; i < 8; i++) rs[i] = 0.f;

  for (int nt = 0; nt < (2 * H / BN) / 2; nt++) {  // 512/128 = 4 column passes
    const int n0 = nt * BN;
    unsigned long long acc[8][4];
#pragma unroll
    for (int i = 0; i < 8; i++)
#pragma unroll
      for (int j = 0; j < 4; j++) acc[i][j] = 0ull;

    for (int k0 = 0; k0 < H; k0 += BK) {
      __syncthreads();
      // Load A tile (128 rows x 16 k) and B tile (128 cols x 16 k), 2 float4 each.
#pragma unroll
      for (int l = 0; l < 2; l++) {
        int f = tid + l * 256;
        int row = f >> 2;
        int kq = (f & 3) << 2;
        float4 av = *reinterpret_cast<const float4*>(
            enc + (size_t)(m0 + row) * H + k0 + kq);
        As2[kq + 0][row] = f32x2_dup(av.x);
        As2[kq + 1][row] = f32x2_dup(av.y);
        As2[kq + 2][row] = f32x2_dup(av.z);
        As2[kq + 3][row] = f32x2_dup(av.w);
        float4 bv = *reinterpret_cast<const float4*>(
            W + (size_t)(n0 + row) * (2 * H) + H + k0 + kq);
        Bs[kq + 0][row] = bv.x;
        Bs[kq + 1][row] = bv.y;
        Bs[kq + 2][row] = bv.z;
        Bs[kq + 3][row] = bv.w;
      }
      __syncthreads();

#pragma unroll
      for (int k = 0; k < BK; k++) {
        unsigned long long ar[8];
#pragma unroll
        for (int i = 0; i < 4; i++) {
          ulonglong2 t = *reinterpret_cast<const ulonglong2*>(&As2[k][ty * 8 + 2 * i]);
          ar[2 * i] = t.x;
          ar[2 * i + 1] = t.y;
        }
        const ulonglong2* bp = reinterpret_cast<const ulonglong2*>(&Bs[k][tx * 8]);
        ulonglong2 b01 = bp[0];
        ulonglong2 b23 = bp[1];
        unsigned long long bb[4] = {b01.x, b01.y, b23.x, b23.y};
#pragma unroll
        for (int i = 0; i < 8; i++)
#pragma unroll
          for (int j = 0; j < 4; j++)
            acc[i][j] = f32x2_fma(ar[i], bb[j], acc[i][j]);
      }
    }

    // Epilogue for this column pass: add P, tanh, dot with v.
    const float4* vp = reinterpret_cast<const float4*>(v + n0 + tx * 8);
    float4 v0 = vp[0];
    float4 v1 = vp[1];
#pragma unroll
    for (int i = 0; i < 8; i++) {
      const float4* pp =
          reinterpret_cast<const float4*>(g_P + segr[i] * H + n0 + tx * 8);
      float4 p0 = pp[0];
      float4 p1 = pp[1];
      float2 a0 = f32x2_unpack(acc[i][0]);
      float2 a1 = f32x2_unpack(acc[i][1]);
      float2 a2 = f32x2_unpack(acc[i][2]);
      float2 a3 = f32x2_unpack(acc[i][3]);
      float t0 = tanhf(a0.x + p0.x);
      float t1 = tanhf(a0.y + p0.y);
      float t2 = tanhf(a1.x + p0.z);
      float t3 = tanhf(a1.y + p0.w);
      float t4 = tanhf(a2.x + p1.x);
      float t5 = tanhf(a2.y + p1.y);
      float t6 = tanhf(a3.x + p1.z);
      float t7 = tanhf(a3.y + p1.w);
      rs[i] += v0.x * t0 + v0.y * t1 + v0.z * t2 + v0.w * t3 +
               v1.x * t4 + v1.y * t5 + v1.z * t6 + v1.w * t7;
    }
  }

  // Deterministic cross-thread reduction of per-row scores.
#pragma unroll
  for (int i = 0; i < 8; i++) red[ty * 8 + i][tx] = rs[i];
  __syncthreads();
  if (tid < BM) {
    float s = 0.f;
#pragma unroll
    for (int j = 0; j < 16; j++) s += red[tid][j];
    g_scores[m0 + tid] = s;
  }
}

// ---------------- Kernel 3: segment softmax (segments sorted) ----------------
__global__ void k_softmax(const int* __restrict__ seg, float* __restrict__ out) {
  int b = blockIdx.x;
  int tid = threadIdx.x;
  __shared__ float sred[256];

  // lower_bound for b and b+1 (seg is sorted ascending)
  int s, e;
  {
    int lo = 0, hi = N_TOK;
    while (lo < hi) {
      int mid = (lo + hi) >> 1;
      if (seg[mid] < b) lo = mid + 1; else hi = mid;
    }
    s = lo;
    hi = N_TOK;
    while (lo < hi) {
      int mid = (lo + hi) >> 1;
      if (seg[mid] < b + 1) lo = mid + 1; else hi = mid;
    }
    e = lo;
  }

  float m = -3.4e38f;
  for (int i = s + tid; i < e; i += 256) m = fmaxf(m, g_scores[i]);
  sred[tid] = m;
  __syncthreads();
  for (int o = 128; o > 0; o >>= 1) {
    if (tid < o) sred[tid] = fmaxf(sred[tid], sred[tid + o]);
    __syncthreads();
  }
  m = sred[0];
  __syncthreads();

  float sum = 0.f;
  for (int i = s + tid; i < e; i += 256) sum += __expf(g_scores[i] - m);
  sred[tid] = sum;
  __syncthreads();
  for (int o = 128; o > 0; o >>= 1) {
    if (tid < o) sred[tid] += sred[tid + o];
    __syncthreads();
  }
  float inv = 1.0f / sred[0];

  for (int i = s + tid; i < e; i += 256) out[i] = __expf(g_scores[i] - m) * inv;
}

// ---------------- launch ----------------
extern "C" void kernel_launch(void* const* d_in, const int* in_sizes, int n_in,
                              void* d_out, int out_size) {
  const float* hidden = (const float*)d_in[0];   // (64, 512)
  const float* enc    = (const float*)d_in[1];   // (131072, 512)
  const int*   seg    = (const int*)d_in[2];     // (131072,)
  const float* W      = (const float*)d_in[3];   // (512, 1024)
  const float* v      = (const float*)d_in[4];   // (512, 1)
  float* out = (float*)d_out;                    // (131072, 1)

  k_precompute_P<<<BATCH, H>>>(hidden, W);
  k_fused<<<N_TOK / BM, 256>>>(enc, seg, W, v);
  k_softmax<<<BATCH, 256>>>(seg, out);
}

// round 5
// speedup vs baseline: 2.4278x; 2.4278x over previous
#include <cuda_runtime.h>
#include <cuda_bf16.h>
#include <math.h>
#include <stdint.h>

#define N_TOK 131072
#define BATCH 64
#define H 512

// Scratch (no cudaMalloc allowed)
__device__ float g_P[BATCH * H];
__device__ float g_scores[N_TOK];
__device__ __nv_bfloat16 g_W2hi[H * H];
__device__ __nv_bfloat16 g_W2lo[H * H];

// ---------------- helpers ----------------
static __device__ __forceinline__ uint32_t cvta_s(const void* p) {
  return (uint32_t)__cvta_generic_to_shared(p);
}
static __device__ __forceinline__ void ldsm4(uint32_t& r0, uint32_t& r1,
                                             uint32_t& r2, uint32_t& r3,
                                             uint32_t a) {
  asm volatile("ldmatrix.sync.aligned.m8n8.x4.shared.b16 {%0,%1,%2,%3}, [%4];"
               : "=r"(r0), "=r"(r1), "=r"(r2), "=r"(r3)
               : "r"(a));
}
static __device__ __forceinline__ void mma16816(float* c, const uint32_t* a,
                                                uint32_t b0, uint32_t b1) {
  asm volatile(
      "mma.sync.aligned.m16n8k16.row.col.f32.bf16.bf16.f32 "
      "{%0,%1,%2,%3}, {%4,%5,%6,%7}, {%8,%9}, {%0,%1,%2,%3};"
      : "+f"(c[0]), "+f"(c[1]), "+f"(c[2]), "+f"(c[3])
      : "r"(a[0]), "r"(a[1]), "r"(a[2]), "r"(a[3]), "r"(b0), "r"(b1));
}
// tanh(x) = (e^{2x}-1)/(e^{2x}+1), computed as 1 - 2/(e+1) (algebraically exact)
static __device__ __forceinline__ float ftanh(float x) {
  float e = __expf(2.0f * x);
  return 1.0f - __fdividef(2.0f, e + 1.0f);
}

// ---------------- Kernel 0: split W2 (cols 512..1023 of W) into bf16 hi/lo ----
__global__ void k_convert_W2(const float* __restrict__ W) {
  int i = blockIdx.x * blockDim.x + threadIdx.x;  // over H*H
  int h = i >> 9, k = i & 511;
  float x = W[h * 1024 + 512 + k];
  __nv_bfloat16 hi = __float2bfloat16_rn(x);
  float r = x - __bfloat162float(hi);
  g_W2hi[i] = hi;
  g_W2lo[i] = __float2bfloat16_rn(r);
}

// ---------------- Kernel 1: P[b,h] = sum_k hidden[b,k] * W[h,k] ----------------
__global__ void k_precompute_P(const float* __restrict__ hidden,
                               const float* __restrict__ W) {
  int b = blockIdx.x;
  int h = threadIdx.x;  // 512 threads
  __shared__ float hs[H];
  hs[h] = hidden[b * H + h];
  __syncthreads();
  const float4* wr = reinterpret_cast<const float4*>(W + (size_t)h * (2 * H));
  float acc = 0.f;
#pragma unroll 8
  for (int k4 = 0; k4 < H / 4; k4++) {
    float4 w = wr[k4];
    const float* hh = &hs[k4 * 4];
    acc += w.x * hh[0] + w.y * hh[1] + w.z * hh[2] + w.w * hh[3];
  }
  g_P[b * H + h] = acc;
}

// ---------------- Kernel 2: fused split-bf16 MMA GEMM + tanh + v-dot ----------
// E2[n,h] = sum_k enc[n,k]*W2[h,k];  score[n] = sum_h v[h]*tanh(P[seg[n],h]+E2[n,h])
#define STRIDE 80            // bytes per smem row (32 bf16 = 64B + 16B pad)
#define TILE 10240           // 128 rows * STRIDE
#define OFF_AHI 0
#define OFF_ALO (2 * TILE)
#define OFF_BHI (4 * TILE)
#define OFF_BLO (6 * TILE)
#define OFF_RED (8 * TILE)   // 81920
#define SMEM_FUSED (OFF_RED + 128 * 2 * 4)  // 82944

__global__ __launch_bounds__(256, 1) void k_fused_mma(
    const float* __restrict__ enc, const int* __restrict__ seg,
    const float* __restrict__ v) {
  extern __shared__ char sm[];
  const int tid = threadIdx.x;
  const int wid = tid >> 5, lid = tid & 31;
  const int wm = wid & 3, wn = wid >> 2;       // 4 x 2 warp grid
  const int m0 = blockIdx.x * 128;
  const int gID = lid >> 2, tig = lid & 3;

  const uint32_t sbase = cvta_s(sm);

  // per-lane ldmatrix byte offsets within one tile buffer
  const uint32_t a_lane = (uint32_t)((wm * 32 + (lid & 15)) * STRIDE + ((lid >> 4) << 4));
  const uint32_t b_lane = (uint32_t)((wn * 64 + (lid & 15)) * STRIDE + ((lid >> 4) << 4));

  // global->smem staging indices: each thread owns (row = tid>>1, k-half = tid&1)
  const int lrow = tid >> 1;
  const int lkh = tid & 1;
  const uint32_t st_off = (uint32_t)(lrow * STRIDE + lkh * 32);

  // epilogue row metadata: 4 rows per thread (2 m-tiles x {gID, gID+8})
  const float* Pb[2][2];
#pragma unroll
  for (int t = 0; t < 2; t++) {
    int r0 = m0 + wm * 32 + t * 16 + gID;
    Pb[t][0] = g_P + (size_t)seg[r0] * H;
    Pb[t][1] = g_P + (size_t)seg[r0 + 8] * H;
  }

  float rsum[2][2] = {{0.f, 0.f}, {0.f, 0.f}};

  for (int pass = 0; pass < 4; pass++) {
    const int n0 = pass * 128;
    float acc[16][4];
#pragma unroll
    for (int i = 0; i < 16; i++)
#pragma unroll
      for (int q = 0; q < 4; q++) acc[i][q] = 0.f;

    const float* aG = enc + (size_t)(m0 + lrow) * H + lkh * 16;
    const uint4* bHG = (const uint4*)(g_W2hi + (size_t)(n0 + lrow) * H + lkh * 16);
    const uint4* bLG = (const uint4*)(g_W2lo + (size_t)(n0 + lrow) * H + lkh * 16);

    float4 aF[4];
    uint4 bH[2], bL[2];

    // ---- stage kc into registers ----
#define LOADG(kc)                                                      \
  do {                                                                 \
    const float4* ap = (const float4*)(aG + (kc) * 32);                \
    aF[0] = ap[0]; aF[1] = ap[1]; aF[2] = ap[2]; aF[3] = ap[3];        \
    bH[0] = bHG[(kc) * 4]; bH[1] = bHG[(kc) * 4 + 1];                  \
    bL[0] = bLG[(kc) * 4]; bL[1] = bLG[(kc) * 4 + 1];                  \
  } while (0)

    // ---- convert + store staged registers into smem buffer `buf` ----
#define STSBUF(buf)                                                           \
  do {                                                                        \
    uint32_t hi8[8], lo8[8];                                                  \
    const float* af = (const float*)aF;                                       \
    _Pragma("unroll") for (int i = 0; i < 8; i++) {                           \
      float x0 = af[2 * i], x1 = af[2 * i + 1];                               \
      __nv_bfloat16 h0 = __float2bfloat16_rn(x0);                             \
      __nv_bfloat16 h1 = __float2bfloat16_rn(x1);                             \
      float l0 = x0 - __bfloat162float(h0);                                   \
      float l1 = x1 - __bfloat162float(h1);                                   \
      hi8[i] = (uint32_t)__bfloat16_as_ushort(h0) |                           \
               ((uint32_t)__bfloat16_as_ushort(h1) << 16);                    \
      lo8[i] = (uint32_t)__bfloat16_as_ushort(__float2bfloat16_rn(l0)) |      \
               ((uint32_t)__bfloat16_as_ushort(__float2bfloat16_rn(l1)) << 16);\
    }                                                                         \
    char* base = sm + (buf) * TILE + st_off;                                  \
    *(uint4*)(base + OFF_AHI) = make_uint4(hi8[0], hi8[1], hi8[2], hi8[3]);   \
    *(uint4*)(base + OFF_AHI + 16) = make_uint4(hi8[4], hi8[5], hi8[6], hi8[7]);\
    *(uint4*)(base + OFF_ALO) = make_uint4(lo8[0], lo8[1], lo8[2], lo8[3]);   \
    *(uint4*)(base + OFF_ALO + 16) = make_uint4(lo8[4], lo8[5], lo8[6], lo8[7]);\
    *(uint4*)(base + OFF_BHI) = bH[0];                                        \
    *(uint4*)(base + OFF_BHI + 16) = bH[1];                                   \
    *(uint4*)(base + OFF_BLO) = bL[0];                                        \
    *(uint4*)(base + OFF_BLO + 16) = bL[1];                                   \
  } while (0)

    LOADG(0);
    STSBUF(0);
    __syncthreads();

    for (int kc = 0; kc < 16; kc++) {
      const int cur = kc & 1;
      if (kc < 15) LOADG(kc + 1);

      const uint32_t abh = sbase + OFF_AHI + cur * TILE + a_lane;
      const uint32_t abl = sbase + OFF_ALO + cur * TILE + a_lane;
      const uint32_t bbh = sbase + OFF_BHI + cur * TILE + b_lane;
      const uint32_t bbl = sbase + OFF_BLO + cur * TILE + b_lane;
#pragma unroll
      for (int s = 0; s < 2; s++) {
        uint32_t ah[2][4], al[2][4];
#pragma unroll
        for (int t = 0; t < 2; t++) {
          ldsm4(ah[t][0], ah[t][1], ah[t][2], ah[t][3],
                abh + t * (16 * STRIDE) + s * 32);
          ldsm4(al[t][0], al[t][1], al[t][2], al[t][3],
                abl + t * (16 * STRIDE) + s * 32);
        }
#pragma unroll
        for (int j2 = 0; j2 < 4; j2++) {
          uint32_t bh[4], bl[4];
          ldsm4(bh[0], bh[1], bh[2], bh[3], bbh + j2 * (16 * STRIDE) + s * 32);
          ldsm4(bl[0], bl[1], bl[2], bl[3], bbl + j2 * (16 * STRIDE) + s * 32);
#pragma unroll
          for (int t = 0; t < 2; t++) {
#pragma unroll
            for (int jj = 0; jj < 2; jj++) {
              float* c = acc[t * 8 + j2 * 2 + jj];
              mma16816(c, ah[t], bh[jj], bh[2 + jj]);  // hi*hi
              mma16816(c, ah[t], bl[jj], bl[2 + jj]);  // hi*lo
              mma16816(c, al[t], bh[jj], bh[2 + jj]);  // lo*hi
            }
          }
        }
      }
      __syncthreads();
      if (kc < 15) {
        STSBUF((kc + 1) & 1);
        __syncthreads();
      }
    }

    // per-pass epilogue: add P, tanh, dot with v (accumulate in registers)
#pragma unroll
    for (int t = 0; t < 2; t++) {
#pragma unroll
      for (int j = 0; j < 8; j++) {
        const int col = n0 + wn * 64 + j * 8 + tig * 2;
        const float2 vv = *(const float2*)(v + col);
        const float* c = acc[t * 8 + j];
        const float2 p0 = *(const float2*)(Pb[t][0] + col);
        const float2 p1 = *(const float2*)(Pb[t][1] + col);
        rsum[t][0] += vv.x * ftanh(c[0] + p0.x) + vv.y * ftanh(c[1] + p0.y);
        rsum[t][1] += vv.x * ftanh(c[2] + p1.x) + vv.y * ftanh(c[3] + p1.y);
      }
    }
  }

  // deterministic reduction: shfl across the 4-lane quad, then smem across warp_n
  float* red = (float*)(sm + OFF_RED);
#pragma unroll
  for (int t = 0; t < 2; t++) {
#pragma unroll
    for (int r = 0; r < 2; r++) {
      float s = rsum[t][r];
      s += __shfl_xor_sync(0xffffffffu, s, 1);
      s += __shfl_xor_sync(0xffffffffu, s, 2);
      if (tig == 0) {
        int row_local = wm * 32 + t * 16 + gID + r * 8;
        red[row_local * 2 + wn] = s;
      }
    }
  }
  __syncthreads();
  if (tid < 128) g_scores[m0 + tid] = red[tid * 2] + red[tid * 2 + 1];
}

// ---------------- Kernel 3: segment softmax (segments sorted) ----------------
__global__ void k_softmax(const int* __restrict__ seg, float* __restrict__ out) {
  int b = blockIdx.x;
  int tid = threadIdx.x;
  __shared__ float sred[256];

  int s, e;
  {
    int lo = 0, hi = N_TOK;
    while (lo < hi) {
      int mid = (lo + hi) >> 1;
      if (seg[mid] < b) lo = mid + 1; else hi = mid;
    }
    s = lo;
    hi = N_TOK;
    while (lo < hi) {
      int mid = (lo + hi) >> 1;
      if (seg[mid] < b + 1) lo = mid + 1; else hi = mid;
    }
    e = lo;
  }

  float m = -3.4e38f;
  for (int i = s + tid; i < e; i += 256) m = fmaxf(m, g_scores[i]);
  sred[tid] = m;
  __syncthreads();
  for (int o = 128; o > 0; o >>= 1) {
    if (tid < o) sred[tid] = fmaxf(sred[tid], sred[tid + o]);
    __syncthreads();
  }
  m = sred[0];
  __syncthreads();

  float sum = 0.f;
  for (int i = s + tid; i < e; i += 256) sum += __expf(g_scores[i] - m);
  sred[tid] = sum;
  __syncthreads();
  for (int o = 128; o > 0; o >>= 1) {
    if (tid < o) sred[tid] += sred[tid + o];
    __syncthreads();
  }
  float inv = 1.0f / sred[0];

  for (int i = s + tid; i < e; i += 256) out[i] = __expf(g_scores[i] - m) * inv;
}

// ---------------- launch ----------------
extern "C" void kernel_launch(void* const* d_in, const int* in_sizes, int n_in,
                              void* d_out, int out_size) {
  const float* hidden = (const float*)d_in[0];   // (64, 512)
  const float* enc    = (const float*)d_in[1];   // (131072, 512)
  const int*   seg    = (const int*)d_in[2];     // (131072,)
  const float* W      = (const float*)d_in[3];   // (512, 1024)
  const float* v      = (const float*)d_in[4];   // (512, 1)
  float* out = (float*)d_out;                    // (131072, 1)

  static bool attr_set = false;
  // cudaFuncSetAttribute is idempotent and not a stream op; safe under capture.
  cudaFuncSetAttribute(k_fused_mma, cudaFuncAttributeMaxDynamicSharedMemorySize,
                       SMEM_FUSED);

  k_convert_W2<<<(H * H) / 256, 256>>>(W);
  k_precompute_P<<<BATCH, H>>>(hidden, W);
  k_fused_mma<<<N_TOK / 128, 256, SMEM_FUSED>>>(enc, seg, v);
  k_softmax<<<BATCH, 256>>>(seg, out);
  (void)attr_set;
}

// round 8
// speedup vs baseline: 2.8265x; 1.1642x over previous
#include <cuda_runtime.h>
#include <cuda_bf16.h>
#include <math.h>
#include <stdint.h>

#define N_TOK 131072
#define BATCH 64
#define H 512

// Scratch (no cudaMalloc allowed)
__device__ float g_P[BATCH * H];
__device__ float g_scores[N_TOK];
__device__ __nv_bfloat16 g_W2hi[H * H];
__device__ __nv_bfloat16 g_W2lo[H * H];
__device__ __nv_bfloat16 g_Ahi[(size_t)N_TOK * H];  // 134 MB
__device__ __nv_bfloat16 g_Alo[(size_t)N_TOK * H];  // 134 MB

// ---------------- helpers ----------------
static __device__ __forceinline__ uint32_t cvta_s(const void* p) {
  return (uint32_t)__cvta_generic_to_shared(p);
}
static __device__ __forceinline__ void ldsm4(uint32_t& r0, uint32_t& r1,
                                             uint32_t& r2, uint32_t& r3,
                                             uint32_t a) {
  asm volatile("ldmatrix.sync.aligned.m8n8.x4.shared.b16 {%0,%1,%2,%3}, [%4];"
               : "=r"(r0), "=r"(r1), "=r"(r2), "=r"(r3)
               : "r"(a));
}
static __device__ __forceinline__ void mma16816(float* c, const uint32_t* a,
                                                uint32_t b0, uint32_t b1) {
  asm volatile(
      "mma.sync.aligned.m16n8k16.row.col.f32.bf16.bf16.f32 "
      "{%0,%1,%2,%3}, {%4,%5,%6,%7}, {%8,%9}, {%0,%1,%2,%3};"
      : "+f"(c[0]), "+f"(c[1]), "+f"(c[2]), "+f"(c[3])
      : "r"(a[0]), "r"(a[1]), "r"(a[2]), "r"(a[3]), "r"(b0), "r"(b1));
}
static __device__ __forceinline__ void cp16(uint32_t dst, const void* src) {
  asm volatile("cp.async.cg.shared.global [%0], [%1], 16;" ::
               "r"(dst), "l"(src));
}
#define CP_COMMIT() asm volatile("cp.async.commit_group;" ::: "memory")
#define CP_WAIT(n) asm volatile("cp.async.wait_group %0;" :: "n"(n) : "memory")

static __device__ __forceinline__ uint32_t pack_bf2(float a, float b) {
  return (uint32_t)__bfloat16_as_ushort(__float2bfloat16_rn(a)) |
         ((uint32_t)__bfloat16_as_ushort(__float2bfloat16_rn(b)) << 16);
}
static __device__ __forceinline__ float bf_res(float x) {
  return x - __bfloat162float(__float2bfloat16_rn(x));
}
// tanh(x) = 1 - 2/(e^{2x}+1) (algebraically exact)
static __device__ __forceinline__ float ftanh(float x) {
  float e = __expf(2.0f * x);
  return 1.0f - __fdividef(2.0f, e + 1.0f);
}

// ---------------- Kernel 0a: split W2 (cols 512..1023 of W) into bf16 hi/lo --
__global__ void k_convert_W2(const float* __restrict__ W) {
  int i = blockIdx.x * blockDim.x + threadIdx.x;
  int h = i >> 9, k = i & 511;
  float x = W[h * 1024 + 512 + k];
  __nv_bfloat16 hi = __float2bfloat16_rn(x);
  g_W2hi[i] = hi;
  g_W2lo[i] = __float2bfloat16_rn(x - __bfloat162float(hi));
}

// ---------------- Kernel 0b: split enc into bf16 hi/lo ----------------------
__global__ void k_convert_A(const float* __restrict__ enc) {
  size_t i = ((size_t)blockIdx.x * 256 + threadIdx.x) * 8;
  const float4* src = reinterpret_cast<const float4*>(enc + i);
  float4 u = src[0], w = src[1];
  uint4 hi = make_uint4(pack_bf2(u.x, u.y), pack_bf2(u.z, u.w),
                        pack_bf2(w.x, w.y), pack_bf2(w.z, w.w));
  uint4 lo = make_uint4(
      pack_bf2(bf_res(u.x), bf_res(u.y)), pack_bf2(bf_res(u.z), bf_res(u.w)),
      pack_bf2(bf_res(w.x), bf_res(w.y)), pack_bf2(bf_res(w.z), bf_res(w.w)));
  *reinterpret_cast<uint4*>(g_Ahi + i) = hi;
  *reinterpret_cast<uint4*>(g_Alo + i) = lo;
}

// ---------------- Kernel 1: P[b,h] = sum_k hidden[b,k] * W[h,k] ------------
__global__ void k_precompute_P(const float* __restrict__ hidden,
                               const float* __restrict__ W) {
  int b = blockIdx.x, hy = blockIdx.y;
  int tid = threadIdx.x;
  int hloc = tid >> 2, part = tid & 3;
  int h = hy * 64 + hloc;
  __shared__ float hs[H];
  __shared__ float red[64][4];
  hs[tid] = hidden[b * H + tid];
  hs[tid + 256] = hidden[b * H + tid + 256];
  __syncthreads();
  const float4* wr =
      reinterpret_cast<const float4*>(W + (size_t)h * (2 * H) + part * 128);
  const float* hh = &hs[part * 128];
  float acc = 0.f;
#pragma unroll 8
  for (int k4 = 0; k4 < 32; k4++) {
    float4 w = wr[k4];
    acc += w.x * hh[k4 * 4] + w.y * hh[k4 * 4 + 1] + w.z * hh[k4 * 4 + 2] +
           w.w * hh[k4 * 4 + 3];
  }
  red[hloc][part] = acc;
  __syncthreads();
  if (tid < 64)
    g_P[b * H + hy * 64 + tid] =
        red[tid][0] + red[tid][1] + red[tid][2] + red[tid][3];
}

// ---------------- Kernel 2: fused split-bf16 MMA GEMM + tanh + v-dot --------
// Tiles 128x128x32, cp.async double buffer, all operands pre-converted bf16.
#define STRIDE 80          // bytes per smem row (32 bf16 = 64B + 16B pad)
#define OPSZ 10240         // 128 rows * STRIDE per operand-half
#define STG 40960          // stage = Ahi,Alo,Bhi,Blo
#define RED_OFF 81920
#define SMEM_FUSED (RED_OFF + 1024)  // 82944

__global__ __launch_bounds__(256, 2) void k_fused_mma(
    const int* __restrict__ seg, const float* __restrict__ v) {
  extern __shared__ char sm[];
  const int tid = threadIdx.x;
  const int wid = tid >> 5, lid = tid & 31;
  const int wm = wid & 3, wn = wid >> 2;  // 4 x 2 warp grid
  const int m0 = blockIdx.x * 128;
  const int gID = lid >> 2, tig = lid & 3;
  const uint32_t sbase = cvta_s(sm);

  // ldmatrix byte offsets within a stage buffer
  const uint32_t a_lane =
      (uint32_t)((wm * 32 + (lid & 15)) * STRIDE + ((lid >> 4) << 4));
  const uint32_t b_lane =
      (uint32_t)((wn * 64 + (lid & 15)) * STRIDE + ((lid >> 4) << 4));

  // cp.async staging: per thread, 2 rows per operand
  const int srow0 = tid >> 2, sc0 = tid & 3;          // id = tid
  const int srow1 = (tid + 256) >> 2, sc1 = tid & 3;  // id = tid + 256

  // epilogue row metadata
  const float* Pb[2][2];
#pragma unroll
  for (int t = 0; t < 2; t++) {
    int r0 = m0 + wm * 32 + t * 16 + gID;
    Pb[t][0] = g_P + (size_t)seg[r0] * H;
    Pb[t][1] = g_P + (size_t)seg[r0 + 8] * H;
  }

  float rsum[2][2] = {{0.f, 0.f}, {0.f, 0.f}};

  for (int pass = 0; pass < 4; pass++) {
    const int n0 = pass * 128;
    float acc[16][4];
#pragma unroll
    for (int i = 0; i < 16; i++)
#pragma unroll
      for (int q = 0; q < 4; q++) acc[i][q] = 0.f;

#define ISSUE_STAGE(kc, buf)                                                 \
  do {                                                                       \
    const uint32_t db = sbase + (buf) * STG;                                 \
    {                                                                        \
      size_t ao = (size_t)(m0 + srow0) * H + (kc) * 32 + sc0 * 8;            \
      size_t bo = (size_t)(n0 + srow0) * H + (kc) * 32 + sc0 * 8;            \
      uint32_t d = db + srow0 * STRIDE + sc0 * 16;                           \
      cp16(d + 0 * OPSZ, g_Ahi + ao);                                        \
      cp16(d + 1 * OPSZ, g_Alo + ao);                                        \
      cp16(d + 2 * OPSZ, g_W2hi + bo);                                       \
      cp16(d + 3 * OPSZ, g_W2lo + bo);                                       \
    }                                                                        \
    {                                                                        \
      size_t ao = (size_t)(m0 + srow1) * H + (kc) * 32 + sc1 * 8;            \
      size_t bo = (size_t)(n0 + srow1) * H + (kc) * 32 + sc1 * 8;            \
      uint32_t d = db + srow1 * STRIDE + sc1 * 16;                           \
      cp16(d + 0 * OPSZ, g_Ahi + ao);                                        \
      cp16(d + 1 * OPSZ, g_Alo + ao);                                        \
      cp16(d + 2 * OPSZ, g_W2hi + bo);                                       \
      cp16(d + 3 * OPSZ, g_W2lo + bo);                                       \
    }                                                                        \
    CP_COMMIT();                                                             \
  } while (0)

    ISSUE_STAGE(0, 0);

    for (int kc = 0; kc < 16; kc++) {
      const int cur = kc & 1;
      if (kc < 15) {
        ISSUE_STAGE(kc + 1, cur ^ 1);
        CP_WAIT(1);
      } else {
        CP_WAIT(0);
      }
      __syncthreads();

      const uint32_t abh = sbase + cur * STG + 0 * OPSZ + a_lane;
      const uint32_t abl = sbase + cur * STG + 1 * OPSZ + a_lane;
      const uint32_t bbh = sbase + cur * STG + 2 * OPSZ + b_lane;
      const uint32_t bbl = sbase + cur * STG + 3 * OPSZ + b_lane;
#pragma unroll
      for (int s = 0; s < 2; s++) {
        uint32_t ah[2][4], al[2][4];
#pragma unroll
        for (int t = 0; t < 2; t++) {
          ldsm4(ah[t][0], ah[t][1], ah[t][2], ah[t][3],
                abh + t * (16 * STRIDE) + s * 32);
          ldsm4(al[t][0], al[t][1], al[t][2], al[t][3],
                abl + t * (16 * STRIDE) + s * 32);
        }
#pragma unroll
        for (int j2 = 0; j2 < 4; j2++) {
          uint32_t bh[4], bl[4];
          ldsm4(bh[0], bh[1], bh[2], bh[3], bbh + j2 * (16 * STRIDE) + s * 32);
          ldsm4(bl[0], bl[1], bl[2], bl[3], bbl + j2 * (16 * STRIDE) + s * 32);
#pragma unroll
          for (int t = 0; t < 2; t++) {
#pragma unroll
            for (int jj = 0; jj < 2; jj++) {
              float* c = acc[t * 8 + j2 * 2 + jj];
              mma16816(c, ah[t], bh[jj], bh[2 + jj]);  // hi*hi
              mma16816(c, ah[t], bl[jj], bl[2 + jj]);  // hi*lo
              mma16816(c, al[t], bh[jj], bh[2 + jj]);  // lo*hi
            }
          }
        }
      }
      __syncthreads();
    }

    // per-pass epilogue: add P, tanh, dot with v
#pragma unroll
    for (int t = 0; t < 2; t++) {
#pragma unroll
      for (int j = 0; j < 8; j++) {
        const int col = n0 + wn * 64 + j * 8 + tig * 2;
        const float2 vv = *(const float2*)(v + col);
        const float* c = acc[t * 8 + j];
        const float2 p0 = *(const float2*)(Pb[t][0] + col);
        const float2 p1 = *(const float2*)(Pb[t][1] + col);
        rsum[t][0] += vv.x * ftanh(c[0] + p0.x) + vv.y * ftanh(c[1] + p0.y);
        rsum[t][1] += vv.x * ftanh(c[2] + p1.x) + vv.y * ftanh(c[3] + p1.y);
      }
    }
  }

  // deterministic reduction: shfl across the 4-lane quad, then smem combine
  float* red = (float*)(sm + RED_OFF);
#pragma unroll
  for (int t = 0; t < 2; t++) {
#pragma unroll
    for (int r = 0; r < 2; r++) {
      float s = rsum[t][r];
      s += __shfl_xor_sync(0xffffffffu, s, 1);
      s += __shfl_xor_sync(0xffffffffu, s, 2);
      if (tig == 0) {
        int row_local = wm * 32 + t * 16 + gID + r * 8;
        red[row_local * 2 + wn] = s;
      }
    }
  }
  __syncthreads();
  if (tid < 128) g_scores[m0 + tid] = red[tid * 2] + red[tid * 2 + 1];
}

// ---------------- Kernel 3: segment softmax (segments sorted) ----------------
__global__ void k_softmax(const int* __restrict__ seg, float* __restrict__ out) {
  int b = blockIdx.x;
  int tid = threadIdx.x;
  __shared__ float sred[256];

  int s, e;
  {
    int lo = 0, hi = N_TOK;
    while (lo < hi) {
      int mid = (lo + hi) >> 1;
      if (seg[mid] < b) lo = mid + 1; else hi = mid;
    }
    s = lo;
    hi = N_TOK;
    while (lo < hi) {
      int mid = (lo + hi) >> 1;
      if (seg[mid] < b + 1) lo = mid + 1; else hi = mid;
    }
    e = lo;
  }

  float m = -3.4e38f;
  for (int i = s + tid; i < e; i += 256) m = fmaxf(m, g_scores[i]);
  sred[tid] = m;
  __syncthreads();
  for (int o = 128; o > 0; o >>= 1) {
    if (tid < o) sred[tid] = fmaxf(sred[tid], sred[tid + o]);
    __syncthreads();
  }
  m = sred[0];
  __syncthreads();

  float sum = 0.f;
  for (int i = s + tid; i < e; i += 256) sum += __expf(g_scores[i] - m);
  sred[tid] = sum;
  __syncthreads();
  for (int o = 128; o > 0; o >>= 1) {
    if (tid < o) sred[tid] += sred[tid + o];
    __syncthreads();
  }
  float inv = 1.0f / sred[0];

  for (int i = s + tid; i < e; i += 256) out[i] = __expf(g_scores[i] - m) * inv;
}

// ---------------- launch ----------------
extern "C" void kernel_launch(void* const* d_in, const int* in_sizes, int n_in,
                              void* d_out, int out_size) {
  const float* hidden = (const float*)d_in[0];   // (64, 512)
  const float* enc    = (const float*)d_in[1];   // (131072, 512)
  const int*   seg    = (const int*)d_in[2];     // (131072,)
  const float* W      = (const float*)d_in[3];   // (512, 1024)
  const float* v      = (const float*)d_in[4];   // (512, 1)
  float* out = (float*)d_out;                    // (131072, 1)

  cudaFuncSetAttribute(k_fused_mma, cudaFuncAttributeMaxDynamicSharedMemorySize,
                       SMEM_FUSED);

  k_convert_W2<<<(H * H) / 256, 256>>>(W);
  k_convert_A<<<(N_TOK * (H / 8)) / 256, 256>>>(enc);
  dim3 pgrid(BATCH, 8);
  k_precompute_P<<<pgrid, 256>>>(hidden, W);
  k_fused_mma<<<N_TOK / 128, 256, SMEM_FUSED>>>(seg, v);
  k_softmax<<<BATCH, 256>>>(seg, out);
}

// round 12
// speedup vs baseline: 3.2895x; 1.1638x over previous
#include <cuda_runtime.h>
#include <cuda_bf16.h>
#include <math.h>
#include <stdint.h>

#define N_TOK 131072
#define BATCH 64
#define H 512

// Scratch (no cudaMalloc allowed)
__device__ float g_P[BATCH * H];
__device__ float g_scores[N_TOK];
__device__ __nv_bfloat16 g_W2hi[H * H];
__device__ __nv_bfloat16 g_W2lo[H * H];
__device__ __nv_bfloat16 g_Ahi[(size_t)N_TOK * H];  // 134 MB
__device__ __nv_bfloat16 g_Alo[(size_t)N_TOK * H];  // 134 MB

// ---------------- helpers ----------------
static __device__ __forceinline__ uint32_t cvta_s(const void* p) {
  return (uint32_t)__cvta_generic_to_shared(p);
}
static __device__ __forceinline__ void ldsm4(uint32_t& r0, uint32_t& r1,
                                             uint32_t& r2, uint32_t& r3,
                                             uint32_t a) {
  asm volatile("ldmatrix.sync.aligned.m8n8.x4.shared.b16 {%0,%1,%2,%3}, [%4];"
               : "=r"(r0), "=r"(r1), "=r"(r2), "=r"(r3)
               : "r"(a));
}
static __device__ __forceinline__ void mma16816(float* c, const uint32_t* a,
                                                uint32_t b0, uint32_t b1) {
  asm volatile(
      "mma.sync.aligned.m16n8k16.row.col.f32.bf16.bf16.f32 "
      "{%0,%1,%2,%3}, {%4,%5,%6,%7}, {%8,%9}, {%0,%1,%2,%3};"
      : "+f"(c[0]), "+f"(c[1]), "+f"(c[2]), "+f"(c[3])
      : "r"(a[0]), "r"(a[1]), "r"(a[2]), "r"(a[3]), "r"(b0), "r"(b1));
}
static __device__ __forceinline__ void cp16(uint32_t dst, const void* src) {
  asm volatile("cp.async.cg.shared.global [%0], [%1], 16;" ::
               "r"(dst), "l"(src));
}
#define CP_COMMIT() asm volatile("cp.async.commit_group;" ::: "memory")
#define CP_WAIT(n) asm volatile("cp.async.wait_group %0;" :: "n"(n) : "memory")

static __device__ __forceinline__ uint32_t pack_bf2(float a, float b) {
  return (uint32_t)__bfloat16_as_ushort(__float2bfloat16_rn(a)) |
         ((uint32_t)__bfloat16_as_ushort(__float2bfloat16_rn(b)) << 16);
}
static __device__ __forceinline__ float bf_res(float x) {
  return x - __bfloat162float(__float2bfloat16_rn(x));
}
// tanh(x) = 1 - 2/(e^{2x}+1) (algebraically exact)
static __device__ __forceinline__ float ftanh(float x) {
  float e = __expf(2.0f * x);
  return 1.0f - __fdividef(2.0f, e + 1.0f);
}

// ---------------- Kernel 0a: split W2 (cols 512..1023 of W) into bf16 hi/lo --
__global__ void k_convert_W2(const float* __restrict__ W) {
  int i = blockIdx.x * blockDim.x + threadIdx.x;
  int h = i >> 9, k = i & 511;
  float x = W[h * 1024 + 512 + k];
  __nv_bfloat16 hi = __float2bfloat16_rn(x);
  g_W2hi[i] = hi;
  g_W2lo[i] = __float2bfloat16_rn(x - __bfloat162float(hi));
}

// ---------------- Kernel 0b: split enc into bf16 hi/lo ----------------------
__global__ void k_convert_A(const float* __restrict__ enc) {
  size_t i = ((size_t)blockIdx.x * 256 + threadIdx.x) * 8;
  const float4* src = reinterpret_cast<const float4*>(enc + i);
  float4 u = src[0], w = src[1];
  uint4 hi = make_uint4(pack_bf2(u.x, u.y), pack_bf2(u.z, u.w),
                        pack_bf2(w.x, w.y), pack_bf2(w.z, w.w));
  uint4 lo = make_uint4(
      pack_bf2(bf_res(u.x), bf_res(u.y)), pack_bf2(bf_res(u.z), bf_res(u.w)),
      pack_bf2(bf_res(w.x), bf_res(w.y)), pack_bf2(bf_res(w.z), bf_res(w.w)));
  *reinterpret_cast<uint4*>(g_Ahi + i) = hi;
  *reinterpret_cast<uint4*>(g_Alo + i) = lo;
}

// ---------------- Kernel 1: P[b,h] = sum_k hidden[b,k] * W[h,k] ------------
__global__ void k_precompute_P(const float* __restrict__ hidden,
                               const float* __restrict__ W) {
  int b = blockIdx.x, hy = blockIdx.y;
  int tid = threadIdx.x;
  int hloc = tid >> 2, part = tid & 3;
  int h = hy * 64 + hloc;
  __shared__ float hs[H];
  __shared__ float red[64][4];
  hs[tid] = hidden[b * H + tid];
  hs[tid + 256] = hidden[b * H + tid + 256];
  __syncthreads();
  const float4* wr =
      reinterpret_cast<const float4*>(W + (size_t)h * (2 * H) + part * 128);
  const float* hh = &hs[part * 128];
  float acc = 0.f;
#pragma unroll 8
  for (int k4 = 0; k4 < 32; k4++) {
    float4 w = wr[k4];
    acc += w.x * hh[k4 * 4] + w.y * hh[k4 * 4 + 1] + w.z * hh[k4 * 4 + 2] +
           w.w * hh[k4 * 4 + 3];
  }
  red[hloc][part] = acc;
  __syncthreads();
  if (tid < 64)
    g_P[b * H + hy * 64 + tid] =
        red[tid][0] + red[tid][1] + red[tid][2] + red[tid][3];
}

// ---------------- Kernel 2: fused split-bf16 MMA GEMM + tanh + v-dot --------
// 128x128x32 tiles; flat 64-chunk loop (4 n-passes x 16 k-chunks);
// ring-3 cp.async pipeline, ONE barrier per chunk; XOR-swizzled 64B rows.
#define OPSZ 8192            // 128 rows * 64B per operand-half
#define STG 32768            // stage = Ahi,Alo,Bhi,Blo
#define RED_OFF 98304        // 3 * STG
#define SMEM_FUSED (RED_OFF + 1024)  // 99328

__global__ __launch_bounds__(256, 2) void k_fused_mma(
    const int* __restrict__ seg, const float* __restrict__ v) {
  extern __shared__ char sm[];
  const int tid = threadIdx.x;
  const int wid = tid >> 5, lid = tid & 31;
  const int wm = wid & 3, wn = wid >> 2;  // 4 x 2 warp grid
  const int m0 = blockIdx.x * 128;
  const int gID = lid >> 2, tig = lid & 3;
  const uint32_t sbase = cvta_s(sm);

  // ---- per-lane ldmatrix constants (XOR swizzle) ----
  const int x15 = lid & 15;
  const int hi16 = lid >> 4;
  const int lswz = (x15 >> 1) & 3;
  const uint32_t akh0 = (uint32_t)((hi16 ^ lswz) * 16);        // k-half 0 atom
  const uint32_t akh1 = (uint32_t)(((2 + hi16) ^ lswz) * 16);  // k-half 1 atom
  const uint32_t arow = (uint32_t)((wm * 32 + x15) * 64);
  const uint32_t brow = (uint32_t)((wn * 64 + x15) * 64);

  // ---- cp.async staging constants: rows tid>>2 and tid>>2+64, atom tid&3 ----
  const int srow0 = tid >> 2, sc = tid & 3;
  const uint32_t sto0 =
      (uint32_t)(srow0 * 64 + ((sc ^ ((srow0 >> 1) & 3)) * 16));
  const uint32_t sto1 = sto0 + 4096;  // row + 64 (same swizzle phase)

  const __nv_bfloat16* pAhi0 = g_Ahi + (size_t)(m0 + srow0) * H + sc * 8;
  const __nv_bfloat16* pAlo0 = g_Alo + (size_t)(m0 + srow0) * H + sc * 8;
  const __nv_bfloat16* pAhi1 = pAhi0 + (size_t)64 * H;
  const __nv_bfloat16* pAlo1 = pAlo0 + (size_t)64 * H;
  const __nv_bfloat16* pBhi0 = g_W2hi + (size_t)srow0 * H + sc * 8;
  const __nv_bfloat16* pBlo0 = g_W2lo + (size_t)srow0 * H + sc * 8;
  const __nv_bfloat16* pBhi1 = pBhi0 + (size_t)64 * H;
  const __nv_bfloat16* pBlo1 = pBlo0 + (size_t)64 * H;

#define ISSUE_STAGE(cc, ib)                                          \
  do {                                                               \
    const uint32_t db = sbase + (uint32_t)(ib) * STG;                \
    const uint32_t eA = (uint32_t)((cc) & 15) * 32u;                 \
    const uint32_t eB = eA + (uint32_t)((cc) >> 4) * 65536u;         \
    cp16(db + sto0, pAhi0 + eA);                                     \
    cp16(db + sto0 + OPSZ, pAlo0 + eA);                              \
    cp16(db + sto0 + 2 * OPSZ, pBhi0 + eB);                          \
    cp16(db + sto0 + 3 * OPSZ, pBlo0 + eB);                          \
    cp16(db + sto1, pAhi1 + eA);                                     \
    cp16(db + sto1 + OPSZ, pAlo1 + eA);                              \
    cp16(db + sto1 + 2 * OPSZ, pBhi1 + eB);                          \
    cp16(db + sto1 + 3 * OPSZ, pBlo1 + eB);                          \
    CP_COMMIT();                                                     \
  } while (0)

  // epilogue row metadata
  const float* Pb[2][2];
#pragma unroll
  for (int t = 0; t < 2; t++) {
    int r0 = m0 + wm * 32 + t * 16 + gID;
    Pb[t][0] = g_P + (size_t)seg[r0] * H;
    Pb[t][1] = g_P + (size_t)seg[r0 + 8] * H;
  }

  float rsum[2][2] = {{0.f, 0.f}, {0.f, 0.f}};
  float acc[16][4];
#pragma unroll
  for (int i = 0; i < 16; i++)
#pragma unroll
    for (int q = 0; q < 4; q++) acc[i][q] = 0.f;

  // prologue: stages 0,1 into bufs 0,1
  ISSUE_STAGE(0, 0);
  ISSUE_STAGE(1, 1);

  int cb = 0;  // compute buffer = c % 3
  int ib = 2;  // issue buffer = (c+2) % 3

  for (int c = 0; c < 64; c++) {
    if (c < 63) { CP_WAIT(1); } else { CP_WAIT(0); }
    __syncthreads();  // all warps done reading buf (c-1)%3 == write target
    if (c < 62) {
      ISSUE_STAGE(c + 2, ib);
      ib = (ib == 2) ? 0 : ib + 1;
    }

    const uint32_t bb = sbase + (uint32_t)cb * STG;
    cb = (cb == 2) ? 0 : cb + 1;
    const uint32_t abh = bb + arow;
    const uint32_t abl = bb + OPSZ + arow;
    const uint32_t bbh = bb + 2 * OPSZ + brow;
    const uint32_t bbl = bb + 3 * OPSZ + brow;

#pragma unroll
    for (int kh = 0; kh < 2; kh++) {
      const uint32_t ak = kh ? akh1 : akh0;
      uint32_t ah[2][4], al[2][4];
#pragma unroll
      for (int t = 0; t < 2; t++) {
        ldsm4(ah[t][0], ah[t][1], ah[t][2], ah[t][3], abh + t * 1024 + ak);
        ldsm4(al[t][0], al[t][1], al[t][2], al[t][3], abl + t * 1024 + ak);
      }
#pragma unroll
      for (int j2 = 0; j2 < 4; j2++) {
        uint32_t bh[4], bl[4];
        ldsm4(bh[0], bh[1], bh[2], bh[3], bbh + j2 * 1024 + ak);
        ldsm4(bl[0], bl[1], bl[2], bl[3], bbl + j2 * 1024 + ak);
#pragma unroll
        for (int t = 0; t < 2; t++) {
#pragma unroll
          for (int jj = 0; jj < 2; jj++) {
            float* cacc = acc[t * 8 + j2 * 2 + jj];
            mma16816(cacc, ah[t], bh[jj], bh[2 + jj]);  // hi*hi
            mma16816(cacc, ah[t], bl[jj], bl[2 + jj]);  // hi*lo
            mma16816(cacc, al[t], bh[jj], bh[2 + jj]);  // lo*hi
          }
        }
      }
    }

    // ---- end of an n-pass: epilogue (register-only; overlaps next loads) ----
    if ((c & 15) == 15) {
      const int n0 = (c >> 4) * 128;
#pragma unroll
      for (int t = 0; t < 2; t++) {
#pragma unroll
        for (int j = 0; j < 8; j++) {
          const int col = n0 + wn * 64 + j * 8 + tig * 2;
          const float2 vv = *(const float2*)(v + col);
          const float* cc2 = acc[t * 8 + j];
          const float2 p0 = *(const float2*)(Pb[t][0] + col);
          const float2 p1 = *(const float2*)(Pb[t][1] + col);
          rsum[t][0] += vv.x * ftanh(cc2[0] + p0.x) + vv.y * ftanh(cc2[1] + p0.y);
          rsum[t][1] += vv.x * ftanh(cc2[2] + p1.x) + vv.y * ftanh(cc2[3] + p1.y);
        }
      }
#pragma unroll
      for (int i = 0; i < 16; i++)
#pragma unroll
        for (int q = 0; q < 4; q++) acc[i][q] = 0.f;
    }
  }

  // deterministic reduction: shfl across the 4-lane quad, then smem combine
  float* red = (float*)(sm + RED_OFF);
#pragma unroll
  for (int t = 0; t < 2; t++) {
#pragma unroll
    for (int r = 0; r < 2; r++) {
      float s = rsum[t][r];
      s += __shfl_xor_sync(0xffffffffu, s, 1);
      s += __shfl_xor_sync(0xffffffffu, s, 2);
      if (tig == 0) {
        int row_local = wm * 32 + t * 16 + gID + r * 8;
        red[row_local * 2 + wn] = s;
      }
    }
  }
  __syncthreads();
  if (tid < 128) g_scores[m0 + tid] = red[tid * 2] + red[tid * 2 + 1];
}

// ---------------- Kernel 3: segment softmax (segments sorted) ----------------
__global__ void k_softmax(const int* __restrict__ seg, float* __restrict__ out) {
  int b = blockIdx.x;
  int tid = threadIdx.x;
  __shared__ float sred[256];

  int s, e;
  {
    int lo = 0, hi = N_TOK;
    while (lo < hi) {
      int mid = (lo + hi) >> 1;
      if (seg[mid] < b) lo = mid + 1; else hi = mid;
    }
    s = lo;
    hi = N_TOK;
    while (lo < hi) {
      int mid = (lo + hi) >> 1;
      if (seg[mid] < b + 1) lo = mid + 1; else hi = mid;
    }
    e = lo;
  }

  float m = -3.4e38f;
  for (int i = s + tid; i < e; i += 256) m = fmaxf(m, g_scores[i]);
  sred[tid] = m;
  __syncthreads();
  for (int o = 128; o > 0; o >>= 1) {
    if (tid < o) sred[tid] = fmaxf(sred[tid], sred[tid + o]);
    __syncthreads();
  }
  m = sred[0];
  __syncthreads();

  float sum = 0.f;
  for (int i = s + tid; i < e; i += 256) sum += __expf(g_scores[i] - m);
  sred[tid] = sum;
  __syncthreads();
  for (int o = 128; o > 0; o >>= 1) {
    if (tid < o) sred[tid] += sred[tid + o];
    __syncthreads();
  }
  float inv = 1.0f / sred[0];

  for (int i = s + tid; i < e; i += 256) out[i] = __expf(g_scores[i] - m) * inv;
}

// ---------------- launch ----------------
extern "C" void kernel_launch(void* const* d_in, const int* in_sizes, int n_in,
                              void* d_out, int out_size) {
  const float* hidden = (const float*)d_in[0];   // (64, 512)
  const float* enc    = (const float*)d_in[1];   // (131072, 512)
  const int*   seg    = (const int*)d_in[2];     // (131072,)
  const float* W      = (const float*)d_in[3];   // (512, 1024)
  const float* v      = (const float*)d_in[4];   // (512, 1)
  float* out = (float*)d_out;                    // (131072, 1)

  cudaFuncSetAttribute(k_fused_mma, cudaFuncAttributeMaxDynamicSharedMemorySize,
                       SMEM_FUSED);

  k_convert_W2<<<(H * H) / 256, 256>>>(W);
  k_convert_A<<<(N_TOK * (H / 8)) / 256, 256>>>(enc);
  dim3 pgrid(BATCH, 8);
  k_precompute_P<<<pgrid, 256>>>(hidden, W);
  k_fused_mma<<<N_TOK / 128, 256, SMEM_FUSED>>>(seg, v);
  k_softmax<<<BATCH, 256>>>(seg, out);
}